// round 1
// baseline (speedup 1.0000x reference)
#include <cuda_runtime.h>
#include <cstdint>

// Problem constants (dataset is fixed shape: tokens [8,4096], IN_FEATURES=1024)
#define NTOK_MAX (8 * 4096)
#define IN_F 1024
#define CUT1 5000
#define CUT2 20000

// Scratch (static device globals — no allocation allowed)
__device__ int g_cnt[2];
__device__ int g_idx0[NTOK_MAX];
__device__ int g_idx1[NTOK_MAX];

// ---------------------------------------------------------------------------
__global__ void init_k() {
    g_cnt[0] = 0;
    g_cnt[1] = 0;
}

// Classify tokens into tail0/tail1 lists with warp-aggregated atomics.
__global__ void classify_k(const int* __restrict__ tokens, int n) {
    int i = blockIdx.x * blockDim.x + threadIdx.x;
    int t = (i < n) ? tokens[i] : -1;
    int c = (t >= CUT2) ? 1 : ((t >= CUT1) ? 0 : -1);
    int lane = threadIdx.x & 31;
#pragma unroll
    for (int cc = 0; cc < 2; ++cc) {
        unsigned m = __ballot_sync(0xffffffffu, c == cc);
        if (c == cc) {
            int leader = __ffs(m) - 1;
            int base = 0;
            if (lane == leader) base = atomicAdd(&g_cnt[cc], __popc(m));
            base = __shfl_sync(m, base, leader);
            int off = base + __popc(m & ((1u << lane) - 1u));
            if (cc == 0) g_idx0[off] = i;
            else         g_idx1[off] = i;
        }
    }
}

// Head cluster: straight gather-copy of a 1024-float row. One block per token.
__global__ void head_copy_k(const int* __restrict__ tokens,
                            const float* __restrict__ head_emb,
                            float* __restrict__ out) {
    int p = blockIdx.x;
    int t = __ldg(&tokens[p]);
    if (t >= CUT1) return;
    const float4* src = (const float4*)(head_emb + (size_t)t * IN_F);
    float4* dst = (float4*)(out + (size_t)p * IN_F);
    dst[threadIdx.x]       = src[threadIdx.x];
    dst[threadIdx.x + 128] = src[threadIdx.x + 128];
}

// ---------------------------------------------------------------------------
// Tail cluster GEMM: out[pos, :] = emb[tok-LOW, :] @ w[:, :]^T  (w is [1024, K])
// Tile: 64 tokens x 64 features, K chunks of 16. 256 threads, 4x4 micro-tile.
template <int K, int LOW, int C>
__global__ void __launch_bounds__(256, 4)
tail_gemm_k(const float* __restrict__ emb,
            const float* __restrict__ w,
            const int* __restrict__ tokens,
            float* __restrict__ out) {
    constexpr int TM = 64, TN = 64, TK = 16, LD = 68;  // LD pad: mild conflicts only
    __shared__ __align__(16) float As[TK][LD];
    __shared__ __align__(16) float Bs[TK][LD];
    __shared__ int sPos[TM];

    const int count = g_cnt[C];
    const int rowBase = blockIdx.x * TM;
    if (rowBase >= count) return;
    const int rem = min(TM, count - rowBase);
    const int n0 = blockIdx.y * TN;
    const int tid = threadIdx.x;
    const int* idxList = (C == 0) ? g_idx0 : g_idx1;

    if (tid < TM) {
        int mm = (tid < rem) ? tid : 0;  // duplicate row 0 for OOB lanes (stores guarded)
        sPos[tid] = idxList[rowBase + mm];
    }
    __syncthreads();

    const int lm  = tid >> 2;   // 0..63 : row within tile (token for A, feature for B)
    const int lkq = tid & 3;    // 0..3  : float4 slot within the 16-wide K chunk
    const int tok = __ldg(&tokens[sPos[lm]]);
    const float* eptr = emb + (size_t)(tok - LOW) * K;
    const float* wptr = w + (size_t)(n0 + lm) * K;

    float acc[4][4];
#pragma unroll
    for (int i = 0; i < 4; i++)
#pragma unroll
        for (int j = 0; j < 4; j++) acc[i][j] = 0.f;

    const int ty = tid >> 4;   // 0..15
    const int tx = tid & 15;   // 0..15

    for (int k0 = 0; k0 < K; k0 += TK) {
        // Global loads issued before the sync: overlap with previous tile's math.
        float4 av = *(const float4*)(eptr + k0 + lkq * 4);
        float4 bv = *(const float4*)(wptr + k0 + lkq * 4);
        __syncthreads();
        As[lkq * 4 + 0][lm] = av.x; As[lkq * 4 + 1][lm] = av.y;
        As[lkq * 4 + 2][lm] = av.z; As[lkq * 4 + 3][lm] = av.w;
        Bs[lkq * 4 + 0][lm] = bv.x; Bs[lkq * 4 + 1][lm] = bv.y;
        Bs[lkq * 4 + 2][lm] = bv.z; Bs[lkq * 4 + 3][lm] = bv.w;
        __syncthreads();
#pragma unroll
        for (int k = 0; k < TK; k++) {
            float4 a4 = *(const float4*)&As[k][ty * 4];
            float4 b4 = *(const float4*)&Bs[k][tx * 4];
            float a[4] = {a4.x, a4.y, a4.z, a4.w};
            float b[4] = {b4.x, b4.y, b4.z, b4.w};
#pragma unroll
            for (int i = 0; i < 4; i++)
#pragma unroll
                for (int j = 0; j < 4; j++) acc[i][j] += a[i] * b[j];
        }
    }

#pragma unroll
    for (int i = 0; i < 4; i++) {
        int m = ty * 4 + i;
        if (m < rem) {
            int pos = sPos[m];
            float4 v = make_float4(acc[i][0], acc[i][1], acc[i][2], acc[i][3]);
            *(float4*)(out + (size_t)pos * IN_F + n0 + tx * 4) = v;
        }
    }
}

// ---------------------------------------------------------------------------
extern "C" void kernel_launch(void* const* d_in, const int* in_sizes, int n_in,
                              void* d_out, int out_size) {
    const int*   tokens   = (const int*)d_in[0];
    const float* head_emb = (const float*)d_in[1];
    const float* t0e      = (const float*)d_in[2];
    const float* t0w      = (const float*)d_in[3];
    const float* t1e      = (const float*)d_in[4];
    const float* t1w      = (const float*)d_in[5];
    float* out = (float*)d_out;
    int n = in_sizes[0];
    if (n > NTOK_MAX) n = NTOK_MAX;

    init_k<<<1, 1>>>();
    classify_k<<<(n + 255) / 256, 256>>>(tokens, n);
    head_copy_k<<<n, 128>>>(tokens, head_emb, out);

    dim3 grid((n + 63) / 64, IN_F / 64);
    tail_gemm_k<512, CUT1, 0><<<grid, 256>>>(t0e, t0w, tokens, out);
    tail_gemm_k<256, CUT2, 1><<<grid, 256>>>(t1e, t1w, tokens, out);
}